// round 14
// baseline (speedup 1.0000x reference)
#include <cuda_runtime.h>
#include <cuda_bf16.h>
#include <math.h>

// ---------------- Problem constants ----------------
#define BB   32
#define TT   1024
#define EE   256
#define HDD  256          // hidden per direction
#define G4   1024         // 4*HD
#define KK   48
#define NEGV (-10000.0f)
#define CPD  64           // CTAs per direction (4 hidden units each)

// ---------------- Device scratch (static; no allocs allowed) ----------------
__device__ float d_hs[2ull * TT * HDD * BB];     // [dir][t][unit][b]
__device__ float d_feats[(size_t)BB * TT * KK];  // [b][t][k]
__device__ int   d_bar[64];                      // spin barrier counters (dir*32)

// ---------------- packed f32x2 helpers (sm_103a FFMA2) ----------------
__device__ __forceinline__ void ffma2(unsigned long long& d,
                                      unsigned long long a,
                                      unsigned long long b) {
    asm("fma.rn.f32x2 %0, %1, %2, %0;" : "+l"(d) : "l"(a), "l"(b));
}
__device__ __forceinline__ float2 unpack2(unsigned long long v) {
    float lo, hi;
    asm("mov.b64 {%0, %1}, %2;" : "=f"(lo), "=f"(hi) : "l"(v));
    return make_float2(lo, hi);
}

__device__ __forceinline__ float sigf(float x) { return 1.0f / (1.0f + expf(-x)); }

// =====================================================================
// Kernel 0: reset barrier counters (fresh for every graph replay)
// =====================================================================
__global__ void k_reset() {
    if (threadIdx.x < 64) d_bar[threadIdx.x] = 0;
}

// =====================================================================
// Kernel 1 (FUSED): persistent bidirectional LSTM with inlined input GEMM.
// grid = 128 CTAs: [0,64) forward, [64,128) backward. CTA owns 4 hidden
// units = 16 gate rows x 32 batches.
//
// Lane decomposition: bp = lane&15 (batch pair 2bp,2bp+1), kh = lane>>4.
// Warp w + kh -> k/e slice of 16: e0 = w*32 + kh*16. 16 slices cover 256.
// Weights pre-duplicated {w,w} in smem (float2) -> FFMA2 with packed
// batch-pair operands, accumulators stay packed, zero per-step packing.
//
// Per step:
//   A: cooperative x-tile load (emb gather -> xs[e][b], pad 34),
//      input matvec into packed acc (independent of barrier -> hides wait)
//   B: barrier wait, h loads (LDG.64 over batch pairs), recurrent matvec
//   C: ps store, reduce over 16 k-slices, bias, cell update, h store,
//      release barrier.
// =====================================================================
__global__ void __launch_bounds__(256, 1) k_fused(
    const int*   __restrict__ sent,
    const float* __restrict__ emb,
    const float* __restrict__ Wih_f, const float* __restrict__ Whh_f,
    const float* __restrict__ bih_f, const float* __restrict__ bhh_f,
    const float* __restrict__ Wih_b, const float* __restrict__ Whh_b,
    const float* __restrict__ bih_b, const float* __restrict__ bhh_b)
{
    extern __shared__ char smraw[];
    float2* wi2 = (float2*)smraw;                               // [16][256] 32 KB
    float2* wh2 = (float2*)(smraw + 32768);                     // [16][256] 32 KB
    float*  xs  = (float*)(smraw + 65536);                      // [256][34] 34 816 B
    float2* ps2 = (float2*)(smraw + 65536 + 34816);             // [16][16][16] 32 KB
    float*  bias_sm = (float*)(smraw + 65536 + 34816 + 32768);  // 16 floats

    int tid  = threadIdx.x;
    int lane = tid & 31;
    int wid  = tid >> 5;
    int dir  = blockIdx.x >> 6;
    int u0   = (blockIdx.x & 63) * 4;

    const float* Wi = dir ? Wih_b : Wih_f;
    const float* Wh = dir ? Whh_b : Whh_f;
    const float* bi = dir ? bih_b : bih_f;
    const float* bh = dir ? bhh_b : bhh_f;

    // one-time: duplicate-pack weight slices into smem.
    // local row r = g*4 + ui  ->  global row g*256 + u0 + ui
    for (int idx = tid; idx < 16 * 256; idx += 256) {
        int r = idx >> 8, k = idx & 255;
        int grow = (r >> 2) * HDD + u0 + (r & 3);
        float wi = Wi[(size_t)grow * EE  + k];
        float wh = Wh[(size_t)grow * HDD + k];
        wi2[idx] = make_float2(wi, wi);
        wh2[idx] = make_float2(wh, wh);
    }
    if (tid < 16) {
        int grow = (tid >> 2) * HDD + u0 + (tid & 3);
        bias_sm[tid] = bi[grow] + bh[grow];
    }
    __syncthreads();

    int bp = lane & 15;
    int kh = lane >> 4;
    int e0 = wid * 32 + kh * 16;
    int ks = wid * 2 + kh;

    int   xrow = tid >> 3;                 // x loader: row 0..31
    int   xa   = tid & 7;                  // x loader: float4 lane 0..7
    float c = 0.f;                         // cell state (tid<128: unit tid>>5, batch lane)
    int   cu = tid >> 5;                   // cell unit (0..3) for tid<128

    size_t hbase = (size_t)dir * TT * HDD * BB;
    int* barp = &d_bar[dir * 32];

    for (int s = 0; s < TT; ++s) {
        int t = dir ? (TT - 1 - s) : s;

        // ---- A0: stage x tile (coalesced gather) ----
        {
            int tok = sent[xrow * TT + t];
            const float4* erow = (const float4*)(emb + (size_t)tok * EE);
#pragma unroll
            for (int j = 0; j < 8; ++j) {
                float4 v = erow[xa + 8 * j];
                int e = (xa + 8 * j) * 4;
                xs[(e + 0) * 34 + xrow] = v.x;
                xs[(e + 1) * 34 + xrow] = v.y;
                xs[(e + 2) * 34 + xrow] = v.z;
                xs[(e + 3) * 34 + xrow] = v.w;
            }
        }
        __syncthreads();

        // ---- A1: input matvec (barrier-independent) ----
        unsigned long long acc2[16];
#pragma unroll
        for (int r = 0; r < 16; ++r) acc2[r] = 0ull;
        {
            unsigned long long x2[16];
            const float* xp = xs + e0 * 34 + 2 * bp;
#pragma unroll
            for (int i = 0; i < 16; ++i)
                x2[i] = *(const unsigned long long*)(xp + i * 34);
#pragma unroll
            for (int r = 0; r < 16; ++r) {
                const ulonglong2* wr = (const ulonglong2*)(wi2 + r * 256 + e0);
#pragma unroll
                for (int i = 0; i < 8; ++i) {
                    ulonglong2 w = wr[i];
                    ffma2(acc2[r], w.x, x2[2 * i]);
                    ffma2(acc2[r], w.y, x2[2 * i + 1]);
                }
            }
        }

        // ---- B: wait for h_{t-1}, recurrent matvec ----
        if (s > 0) {
            if (tid == 0) {
                unsigned tgt = (unsigned)(s << 6);      // 64 CTAs per dir
                unsigned v;
                do {
                    asm volatile("ld.acquire.gpu.global.u32 %0, [%1];"
                                 : "=r"(v) : "l"(barp) : "memory");
                } while (v < tgt);
            }
            __syncthreads();

            int tp = dir ? (t + 1) : (t - 1);
            unsigned long long h2[16];
            const float* hp = &d_hs[hbase + ((size_t)tp * HDD + e0) * BB + 2 * bp];
#pragma unroll
            for (int i = 0; i < 16; ++i)
                h2[i] = *(const unsigned long long*)(hp + (size_t)i * BB);
#pragma unroll
            for (int r = 0; r < 16; ++r) {
                const ulonglong2* wr = (const ulonglong2*)(wh2 + r * 256 + e0);
#pragma unroll
                for (int i = 0; i < 8; ++i) {
                    ulonglong2 w = wr[i];
                    ffma2(acc2[r], w.x, h2[2 * i]);
                    ffma2(acc2[r], w.y, h2[2 * i + 1]);
                }
            }
        }

        // ---- C: partials -> reduce -> cell update -> publish ----
#pragma unroll
        for (int r = 0; r < 16; ++r)
            ps2[(ks * 16 + r) * 16 + bp] = unpack2(acc2[r]);
        __syncthreads();

        if (tid < 128) {                       // unit cu (0..3), batch lane
            const float* pf = (const float*)ps2;   // float view: [ks][r][b]
            float g4[4];
#pragma unroll
            for (int g = 0; g < 4; ++g) {
                int r = g * 4 + cu;
                float sacc = bias_sm[r];
#pragma unroll
                for (int k = 0; k < 16; ++k)
                    sacc += pf[k * 512 + r * 32 + lane];
                g4[g] = sacc;
            }
            c = sigf(g4[1]) * c + sigf(g4[0]) * tanhf(g4[2]);
            float h = sigf(g4[3]) * tanhf(c);
            d_hs[hbase + ((size_t)t * HDD + u0 + cu) * BB + lane] = h;
        }
        __syncthreads();
        if (tid == 0) {
            unsigned one = 1;
            asm volatile("red.release.gpu.global.add.u32 [%0], %1;"
                         :: "l"(barp), "r"(one) : "memory");
        }
    }
}
#define FUSED_SMEM (32768 + 32768 + 34816 + 32768 + 64)

// =====================================================================
// Kernel 2: feats GEMM  feats[b][t][k] = concat(hf,hb)[b][t][:] . W_out[k][:] + b_out[k]
// grid = 1024 (one CTA per t), 256 threads, transposed conflict-free h tile.
// =====================================================================
__global__ void __launch_bounds__(256) k_feats(
    const float* __restrict__ Wout, const float* __restrict__ bout)
{
    __shared__ float hsm[128][33];
    __shared__ __align__(16) float wsm[48][128];

    int tid = threadIdx.x;
    int t   = blockIdx.x;
    int b   = tid & 31;
    int kw  = tid >> 5;

    float acc[6];
#pragma unroll
    for (int p = 0; p < 6; ++p) acc[p] = 0.f;

    for (int cck = 0; cck < 4; ++cck) {
        for (int idx = tid; idx < 128 * 32; idx += 256) {
            int i = idx >> 5, b2 = idx & 31;
            int uu = cck * 128 + i;
            int dd = uu >> 8;
            int u  = uu & 255;
            hsm[i][b2] = d_hs[(((size_t)dd * TT + t) * HDD + u) * BB + b2];
        }
        for (int idx = tid; idx < 48 * 128; idx += 256) {
            int k = idx >> 7, i = idx & 127;
            wsm[k][i] = Wout[(size_t)k * 512 + cck * 128 + i];
        }
        __syncthreads();

#pragma unroll 4
        for (int i4 = 0; i4 < 32; ++i4) {
            float h0 = hsm[i4 * 4 + 0][b];
            float h1 = hsm[i4 * 4 + 1][b];
            float h2v = hsm[i4 * 4 + 2][b];
            float h3 = hsm[i4 * 4 + 3][b];
#pragma unroll
            for (int p = 0; p < 6; ++p) {
                float4 w4 = *(const float4*)&wsm[kw + 8 * p][i4 * 4];
                acc[p] += w4.x * h0 + w4.y * h1 + w4.z * h2v + w4.w * h3;
            }
        }
        __syncthreads();
    }

#pragma unroll
    for (int p = 0; p < 6; ++p) {
        int k = kw + 8 * p;
        d_feats[((size_t)b * TT + t) * KK + k] = acc[p] + bout[k];
    }
}

// =====================================================================
// Kernel 3: Viterbi per batch. 32 CTAs x 64 threads, 6 max-chains.
// =====================================================================
#define VIT_TRP   (48 * 49 * 4)
#define VIT_BPTR  (1024 * 48)
#define VIT_FV    (2 * 48 * 4)
#define VIT_TAGS  (1024 * 4)
#define VIT_SMEM  (VIT_TRP + VIT_BPTR + VIT_FV + VIT_TAGS)

__global__ void __launch_bounds__(64) k_viterbi(
    const float* __restrict__ trans, float* __restrict__ out)
{
    extern __shared__ char sm[];
    float*         trp  = (float*)sm;
    unsigned char* bptr = (unsigned char*)(sm + VIT_TRP);
    float*         fvA  = (float*)(sm + VIT_TRP + VIT_BPTR);
    float*         fvB  = fvA + 48;
    int*           tags = (int*)(sm + VIT_TRP + VIT_BPTR + VIT_FV);
    __shared__ float redsm[64];

    int b = blockIdx.x, tid = threadIdx.x;
    const float* fb = d_feats + (size_t)b * TT * KK;

    for (int idx = tid; idx < 48 * 48; idx += 64)
        trp[(idx / 48) * 49 + (idx % 48)] = trans[idx];
    if (tid < 48) fvA[tid] = (tid == 47) ? 0.f : NEGV;
    __syncthreads();

    float* fv  = fvA;
    float* fvn = fvB;
    const float* trow = &trp[tid * 49];
    for (int t = 0; t < TT; ++t) {
        if (tid < 48) {
            float ft = fb[t * KK + tid];
            float m[6]; int a[6];
#pragma unroll
            for (int cch = 0; cch < 6; ++cch) {
                m[cch] = fv[cch] + trow[cch];
                a[cch] = cch;
            }
#pragma unroll
            for (int jj = 1; jj < 8; ++jj)
#pragma unroll
                for (int cch = 0; cch < 6; ++cch) {
                    int j = jj * 6 + cch;
                    float v = fv[j] + trow[j];
                    if (v > m[cch]) { m[cch] = v; a[cch] = j; }   // strict > = first max
                }
            float M = m[0]; int A = a[0];
#pragma unroll
            for (int cch = 1; cch < 6; ++cch)
                if (m[cch] > M || (m[cch] == M && a[cch] < A)) { M = m[cch]; A = a[cch]; }
            fvn[tid] = M + ft;
            bptr[t * 48 + tid] = (unsigned char)A;
        }
        __syncthreads();
        float* tmp = fv; fv = fvn; fvn = tmp;
    }

    if (tid == 0) {
        float m = -1e30f; int last = 0;
        for (int j = 0; j < 48; ++j)
            if (fv[j] > m) { m = fv[j]; last = j; }
        tags[TT - 1] = last;
        int cur = last;
        for (int t = TT - 2; t >= 0; --t) {
            cur = bptr[(t + 1) * 48 + cur];
            tags[t] = cur;
        }
    }
    __syncthreads();

    for (int t = tid; t < TT; t += 64)
        out[32 + b * TT + t] = (float)tags[t];

    float s = 0.f;
    for (int t = tid; t < TT - 1; t += 64)
        s += trp[tags[t] * 49 + tags[t + 1]];
    for (int t = tid; t < TT; t += 64)
        if (t >= 1) s += fb[t * KK + tags[t]];
    redsm[tid] = s;
    __syncthreads();
    if (tid == 0) {
        float tot = fb[(TT - 1) * KK + tags[0]];
        for (int i = 0; i < 64; ++i) tot += redsm[i];
        out[b] = tot;
    }
}

// =====================================================================
extern "C" void kernel_launch(void* const* d_in, const int* in_sizes, int n_in,
                              void* d_out, int out_size)
{
    const int*   sent  = (const int*)  d_in[0];
    const float* emb   = (const float*)d_in[1];
    const float* Wih_f = (const float*)d_in[2];
    const float* Whh_f = (const float*)d_in[3];
    const float* bih_f = (const float*)d_in[4];
    const float* bhh_f = (const float*)d_in[5];
    const float* Wih_b = (const float*)d_in[6];
    const float* Whh_b = (const float*)d_in[7];
    const float* bih_b = (const float*)d_in[8];
    const float* bhh_b = (const float*)d_in[9];
    const float* W_out = (const float*)d_in[10];
    const float* b_out = (const float*)d_in[11];
    const float* trans = (const float*)d_in[12];
    float* out = (float*)d_out;

    cudaFuncSetAttribute(k_fused,   cudaFuncAttributeMaxDynamicSharedMemorySize, FUSED_SMEM);
    cudaFuncSetAttribute(k_viterbi, cudaFuncAttributeMaxDynamicSharedMemorySize, 65536);

    k_reset<<<1, 64>>>();

    k_fused<<<2 * CPD, 256, FUSED_SMEM>>>(sent, emb,
                                          Wih_f, Whh_f, bih_f, bhh_f,
                                          Wih_b, Whh_b, bih_b, bhh_b);

    k_feats<<<TT, 256>>>(W_out, b_out);

    k_viterbi<<<BB, 64, VIT_SMEM>>>(trans, out);
}

// round 15
// speedup vs baseline: 1.1714x; 1.1714x over previous
#include <cuda_runtime.h>
#include <cuda_bf16.h>
#include <math.h>

// ---------------- Problem constants ----------------
#define BB   32
#define TT   1024
#define EE   256
#define HDD  256          // hidden per direction
#define G4   1024         // 4*HD
#define KK   48
#define NEGV (-10000.0f)

// ---------------- Device scratch (static; no allocs allowed) ----------------
__device__ float d_G[2ull * TT * G4 * BB];       // [dir][t][gate_row][b]
__device__ float d_hs[2ull * TT * HDD * BB];     // [dir][t][unit][b]
__device__ float d_feats[(size_t)BB * TT * KK];  // [b][t][k]
__device__ int   d_bar[64];                      // spin barrier counters (dir*32)

__device__ __forceinline__ float sigf(float x) { return 1.0f / (1.0f + expf(-x)); }

// =====================================================================
// Kernel 0: reset barrier counters (fresh for every graph replay)
// =====================================================================
__global__ void k_reset() {
    if (threadIdx.x < 64) d_bar[threadIdx.x] = 0;
}

// =====================================================================
// Kernel 1: fused embedding-gather + input GEMM (+ bih + bhh)  [R12 proven]
// M = 32768 tokens (token = t*32+b), N = 2048 (2 dirs x 1024), K = 256
// CTA tile 64x64, 256 threads, 4x4 microtile, K-chunk 16.
// =====================================================================
__global__ void __launch_bounds__(256) k_gemm_in(
    const int*   __restrict__ sent,
    const float* __restrict__ emb,
    const float* __restrict__ Wf,  const float* __restrict__ Wb,
    const float* __restrict__ bif, const float* __restrict__ bhf,
    const float* __restrict__ bib, const float* __restrict__ bhb)
{
    __shared__ __align__(16) float aT[16][68];
    __shared__ __align__(16) float wT[16][68];
    __shared__ int tok[64];

    int tid = threadIdx.x;
    int mt  = blockIdx.x;
    int nt  = blockIdx.y;
    int d   = nt >> 4;
    int rbase = (nt & 15) * 64;
    const float* W = d ? Wb : Wf;

    if (tid < 64) {
        int token = mt * 64 + tid;
        int t = token >> 5, b = token & 31;
        tok[tid] = sent[b * TT + t];
    }
    __syncthreads();

    float acc[4][4];
#pragma unroll
    for (int i = 0; i < 4; ++i)
#pragma unroll
        for (int j = 0; j < 4; ++j) acc[i][j] = 0.f;

    int lm = tid >> 2;
    int kq = (tid & 3) * 4;
    int mx = tid & 15;
    int nx = tid >> 4;

    for (int kc = 0; kc < EE; kc += 16) {
        float4 av = *(const float4*)&emb[(size_t)tok[lm] * EE + kc + kq];
        float4 wv = *(const float4*)&W[(size_t)(rbase + lm) * EE + kc + kq];
        __syncthreads();
        aT[kq + 0][lm] = av.x; aT[kq + 1][lm] = av.y;
        aT[kq + 2][lm] = av.z; aT[kq + 3][lm] = av.w;
        wT[kq + 0][lm] = wv.x; wT[kq + 1][lm] = wv.y;
        wT[kq + 2][lm] = wv.z; wT[kq + 3][lm] = wv.w;
        __syncthreads();
#pragma unroll
        for (int k = 0; k < 16; ++k) {
            float4 a4 = *(const float4*)&aT[k][mx * 4];
            float4 w4 = *(const float4*)&wT[k][nx * 4];
            float aa[4] = {a4.x, a4.y, a4.z, a4.w};
            float ww[4] = {w4.x, w4.y, w4.z, w4.w};
#pragma unroll
            for (int ni = 0; ni < 4; ++ni)
#pragma unroll
                for (int mi = 0; mi < 4; ++mi)
                    acc[ni][mi] += ww[ni] * aa[mi];
        }
    }

    const float* bi = d ? bib : bif;
    const float* bh = d ? bhb : bhf;
    int token0 = mt * 64 + mx * 4;
    int t  = token0 >> 5;
    int b0 = token0 & 31;
#pragma unroll
    for (int ni = 0; ni < 4; ++ni) {
        int r = rbase + nx * 4 + ni;
        float bias = bi[r] + bh[r];
        float4 o;
        o.x = acc[ni][0] + bias; o.y = acc[ni][1] + bias;
        o.z = acc[ni][2] + bias; o.w = acc[ni][3] + bias;
        *(float4*)&d_G[(((size_t)d * TT + t) * G4 + r) * BB + b0] = o;
    }
}

// =====================================================================
// Kernel 2: persistent bidirectional LSTM recurrence [R12 compute,
// acquire/release barrier + folded reduce]
// grid = 128 CTAs: [0,64) fwd, [64,128) bwd. CTA owns 4 hidden units
// (16 gate rows) x 32 batches. 8 warps = 8 k-slices of 32, lane = batch.
// =====================================================================
__global__ void __launch_bounds__(256, 1) k_lstm(
    const float* __restrict__ Whf, const float* __restrict__ Whb)
{
    __shared__ __align__(16) float w_sm[16][256];  // 16 KB
    __shared__ float ps[8][16][32];                // 16 KB partials

    int tid  = threadIdx.x;
    int lane = tid & 31;                           // batch
    int wid  = tid >> 5;                           // k-slice / warp id
    int dir  = blockIdx.x >> 6;
    int u0   = (blockIdx.x & 63) * 4;
    const float* Wh = dir ? Whb : Whf;

    for (int idx = tid; idx < 16 * 256; idx += 256) {
        int r = idx >> 8, k = idx & 255;
        int grow = (r >> 2) * HDD + u0 + (r & 3);
        w_sm[r][k] = Wh[(size_t)grow * HDD + k];
    }
    __syncthreads();

    float c = 0.f;
    int ui = wid & 3;                               // cell unit for tid<128
    size_t gbase = (size_t)dir * TT * G4 * BB;
    size_t hbase = (size_t)dir * TT * HDD * BB;
    int* barp = &d_bar[dir * 32];

    for (int s = 0; s < TT; ++s) {
        int t = dir ? (TT - 1 - s) : s;

        // input-gate contributions: independent of barrier, load early
        float gin[4];
        if (tid < 128) {
#pragma unroll
            for (int g = 0; g < 4; ++g)
                gin[g] = d_G[gbase + ((size_t)t * G4 + g * HDD + u0 + ui) * BB + lane];
        }

        if (s > 0) {
            if (tid == 0) {
                unsigned tgt = (unsigned)(s << 6);   // 64 CTAs per dir
                unsigned v;
                do {
                    asm volatile("ld.acquire.gpu.global.u32 %0, [%1];"
                                 : "=r"(v) : "l"(barp) : "memory");
                } while (v < tgt);
            }
            __syncthreads();
        }

        float acc[16];
#pragma unroll
        for (int r = 0; r < 16; ++r) acc[r] = 0.f;

        if (s > 0) {
            int tp = dir ? (t + 1) : (t - 1);
            const float* hp = &d_hs[hbase + ((size_t)tp * HDD + wid * 32) * BB + lane];
            float h_reg[32];
#pragma unroll
            for (int i = 0; i < 32; ++i) h_reg[i] = hp[(size_t)i * 32];
#pragma unroll
            for (int r = 0; r < 16; ++r) {
#pragma unroll
                for (int i4 = 0; i4 < 8; ++i4) {
                    float4 w4 = *(const float4*)&w_sm[r][wid * 32 + i4 * 4];
                    acc[r] += w4.x * h_reg[i4 * 4 + 0];
                    acc[r] += w4.y * h_reg[i4 * 4 + 1];
                    acc[r] += w4.z * h_reg[i4 * 4 + 2];
                    acc[r] += w4.w * h_reg[i4 * 4 + 3];
                }
            }
        }

#pragma unroll
        for (int r = 0; r < 16; ++r) ps[wid][r][lane] = acc[r];
        __syncthreads();

        // cell update with folded 8-way reduce: tid<128 -> (unit u0+ui, batch lane)
        if (tid < 128) {
            float gi = gin[0], gf = gin[1], gg = gin[2], go = gin[3];
#pragma unroll
            for (int w = 0; w < 8; ++w) {
                gi += ps[w][ui][lane];
                gf += ps[w][ui + 4][lane];
                gg += ps[w][ui + 8][lane];
                go += ps[w][ui + 12][lane];
            }
            c = sigf(gf) * c + sigf(gi) * tanhf(gg);
            float h = sigf(go) * tanhf(c);
            d_hs[hbase + ((size_t)t * HDD + u0 + ui) * BB + lane] = h;
        }
        __syncthreads();
        if (tid == 0) {
            unsigned one = 1;
            asm volatile("red.release.gpu.global.add.u32 [%0], %1;"
                         :: "l"(barp), "r"(one) : "memory");
        }
    }
}

// =====================================================================
// Kernel 3: feats GEMM (transposed conflict-free h tile)
// =====================================================================
__global__ void __launch_bounds__(256) k_feats(
    const float* __restrict__ Wout, const float* __restrict__ bout)
{
    __shared__ float hsm[128][33];
    __shared__ __align__(16) float wsm[48][128];

    int tid = threadIdx.x;
    int t   = blockIdx.x;
    int b   = tid & 31;
    int kw  = tid >> 5;

    float acc[6];
#pragma unroll
    for (int p = 0; p < 6; ++p) acc[p] = 0.f;

    for (int cck = 0; cck < 4; ++cck) {
        for (int idx = tid; idx < 128 * 32; idx += 256) {
            int i = idx >> 5, b2 = idx & 31;
            int uu = cck * 128 + i;
            int dd = uu >> 8;
            int u  = uu & 255;
            hsm[i][b2] = d_hs[(((size_t)dd * TT + t) * HDD + u) * BB + b2];
        }
        for (int idx = tid; idx < 48 * 128; idx += 256) {
            int k = idx >> 7, i = idx & 127;
            wsm[k][i] = Wout[(size_t)k * 512 + cck * 128 + i];
        }
        __syncthreads();

#pragma unroll 4
        for (int i4 = 0; i4 < 32; ++i4) {
            float h0 = hsm[i4 * 4 + 0][b];
            float h1 = hsm[i4 * 4 + 1][b];
            float h2v = hsm[i4 * 4 + 2][b];
            float h3 = hsm[i4 * 4 + 3][b];
#pragma unroll
            for (int p = 0; p < 6; ++p) {
                float4 w4 = *(const float4*)&wsm[kw + 8 * p][i4 * 4];
                acc[p] += w4.x * h0 + w4.y * h1 + w4.z * h2v + w4.w * h3;
            }
        }
        __syncthreads();
    }

#pragma unroll
    for (int p = 0; p < 6; ++p) {
        int k = kw + 8 * p;
        d_feats[((size_t)b * TT + t) * KK + k] = acc[p] + bout[k];
    }
}

// =====================================================================
// Kernel 4: Viterbi, REWORKED.
// 32 CTAs x 128 threads. Feats staged in 128-step smem chunks (no LDG
// on the recurrent path). 2 threads per tag: each scans 24 sources in
// 6 independent chains; pair merged with one shfl_xor. First-max
// (jnp.argmax) semantics preserved exactly.
// =====================================================================
#define FCH 128
#define VIT_TRP   (48 * 49 * 4)                    // 9408
#define VIT_BPTR  (1024 * 48)                      // 49152
#define VIT_FV    (2 * 48 * 4)                     // 384
#define VIT_TAGS  (1024 * 4)                       // 4096
#define VIT_FCH   (FCH * 48 * 4)                   // 24576
#define VIT_SMEM  (VIT_TRP + VIT_BPTR + VIT_FV + VIT_TAGS + VIT_FCH)

__global__ void __launch_bounds__(128) k_viterbi(
    const float* __restrict__ trans, float* __restrict__ out)
{
    extern __shared__ char sm[];
    float*         trp  = (float*)sm;                                   // [48][49]
    unsigned char* bptr = (unsigned char*)(sm + VIT_TRP);               // [1024][48]
    float*         fvA  = (float*)(sm + VIT_TRP + VIT_BPTR);
    float*         fvB  = fvA + 48;
    int*           tags = (int*)(sm + VIT_TRP + VIT_BPTR + VIT_FV);
    float*         fch  = (float*)(sm + VIT_TRP + VIT_BPTR + VIT_FV + VIT_TAGS);
    __shared__ float redsm[128];

    int b = blockIdx.x, tid = threadIdx.x;
    const float* fb = d_feats + (size_t)b * TT * KK;

    for (int idx = tid; idx < 48 * 48; idx += 128)
        trp[(idx / 48) * 49 + (idx % 48)] = trans[idx];
    if (tid < 48) fvA[tid] = (tid == 47) ? 0.f : NEGV;

    int tag  = tid >> 1;                 // valid for tid<96 (warps 0-2 fully active)
    int half = tid & 1;                  // 0: sources 0..23, 1: 24..47
    const float* trow = &trp[tag * 49 + half * 24];

    float* fv  = fvA;
    float* fvn = fvB;

    for (int tc = 0; tc < TT; tc += FCH) {
        __syncthreads();                 // fch reuse + (first iter) trp/fv init
        // stage feats chunk: FCH rows x 48 floats = 1536 float4, coalesced
        {
            const float4* src = (const float4*)(fb + (size_t)tc * KK);
            float4* dst = (float4*)fch;
            for (int i = tid; i < FCH * 12; i += 128) dst[i] = src[i];
        }
        __syncthreads();

        for (int tl = 0; tl < FCH; ++tl) {
            if (tid < 96) {
                const float* fvh = fv + half * 24;
                float m[6]; int a[6];
#pragma unroll
                for (int cch = 0; cch < 6; ++cch) {
                    m[cch] = fvh[cch] + trow[cch];
                    a[cch] = cch;
                }
#pragma unroll
                for (int jj = 1; jj < 4; ++jj)
#pragma unroll
                    for (int cch = 0; cch < 6; ++cch) {
                        int j = jj * 6 + cch;
                        float v = fvh[j] + trow[j];
                        if (v > m[cch]) { m[cch] = v; a[cch] = j; }  // strict > = first max
                    }
                float M = m[0]; int A = a[0];
#pragma unroll
                for (int cch = 1; cch < 6; ++cch)
                    if (m[cch] > M || (m[cch] == M && a[cch] < A)) { M = m[cch]; A = a[cch]; }

                // pair exchange (lanes tid, tid^1 are the two halves of one tag)
                float Mo = __shfl_xor_sync(0xffffffffu, M, 1);
                int   Ao = __shfl_xor_sync(0xffffffffu, A, 1);
                if (half == 0) {
                    // half1's indices are all > half0's: strict > keeps first-max
                    float Mg; int Ag;
                    if (Mo > M) { Mg = Mo; Ag = 24 + Ao; }
                    else        { Mg = M;  Ag = A; }
                    fvn[tag] = Mg + fch[tl * 48 + tag];
                    bptr[(tc + tl) * 48 + tag] = (unsigned char)Ag;
                }
            }
            __syncthreads();
            float* tmp = fv; fv = fvn; fvn = tmp;
        }
    }

    // backtrack (sequential, smem-resident)
    if (tid == 0) {
        float m = -1e30f; int last = 0;
        for (int j = 0; j < 48; ++j)
            if (fv[j] > m) { m = fv[j]; last = j; }
        tags[TT - 1] = last;
        int cur = last;
        for (int t = TT - 2; t >= 0; --t) {
            cur = bptr[(t + 1) * 48 + cur];
            tags[t] = cur;
        }
    }
    __syncthreads();

    // emit tags (output layout: score[32] then tags[32][1024])
    for (int t = tid; t < TT; t += 128)
        out[32 + b * TT + t] = (float)tags[t];

    // score = feats[b][T-1][tags[0]]
    //       + sum_{t<T-1} trans[tags[t]][tags[t+1]]
    //       + sum_{t>=1} feats[b][t][tags[t]]
    float s = 0.f;
    for (int t = tid; t < TT - 1; t += 128)
        s += trp[tags[t] * 49 + tags[t + 1]];
    for (int t = tid; t < TT; t += 128)
        if (t >= 1) s += fb[t * KK + tags[t]];
    redsm[tid] = s;
    __syncthreads();
    if (tid == 0) {
        float tot = fb[(TT - 1) * KK + tags[0]];
        for (int i = 0; i < 128; ++i) tot += redsm[i];
        out[b] = tot;
    }
}

// =====================================================================
extern "C" void kernel_launch(void* const* d_in, const int* in_sizes, int n_in,
                              void* d_out, int out_size)
{
    const int*   sent  = (const int*)  d_in[0];
    const float* emb   = (const float*)d_in[1];
    const float* Wih_f = (const float*)d_in[2];
    const float* Whh_f = (const float*)d_in[3];
    const float* bih_f = (const float*)d_in[4];
    const float* bhh_f = (const float*)d_in[5];
    const float* Wih_b = (const float*)d_in[6];
    const float* Whh_b = (const float*)d_in[7];
    const float* bih_b = (const float*)d_in[8];
    const float* bhh_b = (const float*)d_in[9];
    const float* W_out = (const float*)d_in[10];
    const float* b_out = (const float*)d_in[11];
    const float* trans = (const float*)d_in[12];
    float* out = (float*)d_out;

    cudaFuncSetAttribute(k_viterbi, cudaFuncAttributeMaxDynamicSharedMemorySize, VIT_SMEM);

    k_reset<<<1, 64>>>();

    dim3 g1(512, 32);
    k_gemm_in<<<g1, 256>>>(sent, emb, Wih_f, Wih_b, bih_f, bhh_f, bih_b, bhh_b);

    k_lstm<<<128, 256>>>(Whh_f, Whh_b);

    k_feats<<<TT, 256>>>(W_out, b_out);

    k_viterbi<<<BB, 128, VIT_SMEM>>>(trans, out);
}